// round 14
// baseline (speedup 1.0000x reference)
#include <cuda_runtime.h>
#include <math.h>

// Bit-exact replication of the JAX reference on XLA:CPU (validated R9/R12/R13,
// rel_err=0.0). FP op shapes FROZEN:
//   - outside fori_loop: plain __f*_rn ops in reference association order
//   - inside fori_loop body: FMA-contracted F/Fp
//   - exp = fused-Cephes GenerateVF32Exp
// R14 perf change (FP stream untouched): 2 elements per thread. Two
// independent Newton chains interleave inside one thread, hiding the ~45-cycle
// serial step latency that R13 exposed (issue% 90->87). float2 loads/stores.
// Pair-stepping a closed chain is bit-exact (fixed point idempotent; 2-cycle
// stepped in pairs keeps its even-parity value = s50 since 50 is even), so the
// combined exit needs no freeze logic.

__device__ __forceinline__ float xla_vf32_exp(float x)
{
    x = fminf(x, 88.3762626647950f);
    x = fmaxf(x, -88.3762626647949f);

    float fx = floorf(fmaf(x, 1.44269504088896341f, 0.5f));

    float tmp = __fmul_rn(fx, 0.693359375f);
    float z   = __fmul_rn(fx, -2.12194440e-4f);
    x = __fsub_rn(x, tmp);
    x = __fsub_rn(x, z);

    float zz = __fmul_rn(x, x);

    float y = 1.9875691500e-4f;
    y = fmaf(y, x, 1.3981999507e-3f);
    y = fmaf(y, x, 8.3334519073e-3f);
    y = fmaf(y, x, 4.1665795894e-2f);
    y = fmaf(y, x, 1.6666665459e-1f);
    y = fmaf(y, x, 5.0000001201e-1f);
    y = fmaf(y, zz, x);
    y = __fadd_rn(y, 1.0f);

    int emm0 = (int)fx + 127;
    float pow2n = __int_as_float(emm0 << 23);
    return __fmul_rn(y, pow2n);
}

// One EXACT Newton step (bit-frozen op shapes — do not modify).
__device__ __forceinline__ float newton_step(float Te, float B, float C,
                                             float C2, float D)
{
    const float A_CONST = 5.4e-8f;
    const float A4      = (float)(4.0 * 5.4e-8);
    float t   = __fadd_rn(Te, 273.16f);
    float t2  = __fmul_rn(t, t);
    float t4  = __fmul_rn(t2, t2);
    float t3  = __fmul_rn(t2, t);
    float m2  = __fmul_rn(C, __fmul_rn(Te, Te));
    float F   = __fsub_rn(fmaf(B, Te, fmaf(A_CONST, t4, -m2)), D);
    float c2t = __fmul_rn(C2, Te);
    float Fp  = __fadd_rn(fmaf(A4, t3, -c2t), B);
    return __fsub_rn(Te, __fdiv_rn(F, Fp));
}

// Full prologue for one element: computes B, C, C2, D (frozen shapes).
__device__ __forceinline__ void prologue(
    float ta, float ea, float st, float cf, float Ein,
    float elev, float tg, float sfrv, float alb, float sw,
    float& B, float& C, float& C2, float& D)
{
    const float A_CONST = 5.4e-8f; (void)A_CONST;
    const float EV_STB  = (float)(0.9 * 5.670373e-8);
    const float C2495E6 = (float)(2495.0 * 1e6);

    float arg = __fdiv_rn(__fmul_rn(17.26939f, ta), __fadd_rn(237.3f, ta));
    float es  = __fmul_rn(6.108f, xla_vf32_exp(arg));

    float P = __fsub_rn(1013.0f, __fmul_rn(0.1055f, elev));

    float denom  = __fsub_rn(es, ea);
    float denom1 = __fmul_rn(denom, (denom >= 0.0f) ? 1.0f : 0.0f);
    float denom2 = __fadd_rn(denom1, (denom1 == 0.0f) ? 0.01f : 0.0f);
    float Bc = __fdiv_rn(__fmul_rn(0.00061f, P), denom2);

    float tk  = __fadd_rn(ta, 273.16f);
    float tk2 = __fmul_rn(tk, tk);
    float Tk4 = __fmul_rn(tk2, tk2);

    float h1 = __fadd_rn(3.354939e-8f, __fmul_rn(2.74995e-9f, __fsqrt_rn(ea)));
    float h2 = __fsub_rn(1.0f, st);
    float h3 = __fadd_rn(1.0f, __fmul_rn(0.17f, __fmul_rn(cf, cf)));
    float Ha = __fmul_rn(__fmul_rn(__fmul_rn(h1, h2), h3), Tk4);

    float Hs = __fmul_rn(__fmul_rn(__fsub_rn(1.0f, alb), h2), sw);

    float Hv = __fmul_rn(__fmul_rn(EV_STB, sfrv), Tk4);

    float Em = __fmul_rn(1e6f, Ein);
    float b2 = __fadd_rn(2495.0f, __fmul_rn(2.36f, ta));
    float b4 = __fsub_rn(__fmul_rn(Bc, b2), 2.36f);
    B  = __fadd_rn(__fmul_rn(Em, b4), 1.65f);

    C = __fmul_rn(__fmul_rn(Em, Bc), 2.36f);

    float d3 = __fsub_rn(__fmul_rn(Bc, ta), 1.0f);
    float d4 = __fmul_rn(__fmul_rn(C2495E6, Ein), d3);
    float d5 = __fmul_rn(tg, 1.65f);
    D  = __fadd_rn(__fadd_rn(__fadd_rn(__fadd_rn(Ha, Hs), Hv), d4), d5);

    C2 = __fmul_rn(2.0f, C);
}

// Epilogue for one element: Hi, K1, K2 (frozen shapes).
__device__ __forceinline__ void epilogue(
    float Te, float t0, float B, float C, float C2, float D,
    float& K1, float& K2)
{
    const float A_CONST = 5.4e-8f;
    const float A4      = (float)(4.0 * 5.4e-8);

    float u    = __fadd_rn(t0, 273.16f);
    float u2   = __fmul_rn(u, u);
    float u4   = __fmul_rn(u2, u2);
    float t0sq = __fmul_rn(t0, t0);
    float Hi   = __fsub_rn(
                   __fadd_rn(
                     __fsub_rn(__fmul_rn(A_CONST, u4), __fmul_rn(C, t0sq)),
                     __fmul_rn(B, t0)),
                   D);

    float v  = __fadd_rn(Te, 273.16f);
    float v2 = __fmul_rn(v, v);
    float v3 = __fmul_rn(v2, v);
    K1 = __fadd_rn(
           __fsub_rn(__fmul_rn(A4, v3), __fmul_rn(C2, Te)),
           B);

    float delt = __fsub_rn(t0, Te);
    float den  = __fmul_rn(delt, delt);
    float den1 = __fadd_rn(den, (den <= 1e-10f) ? 1.0f : 0.0f);
    K2 = __fdiv_rn(__fsub_rn(__fmul_rn(K1, delt), Hi), den1);
    if (fabsf(delt) < 1e-10f) K2 = 0.0f;
}

__global__ void sntemp_kernel(
    const float* __restrict__ T_a,
    const float* __restrict__ swrad,
    const float* __restrict__ e_a,
    const float* __restrict__ E,
    const float* __restrict__ elev,
    const float* __restrict__ T_g,
    const float* __restrict__ sfr,
    const float* __restrict__ albedo,
    const float* __restrict__ shade_total,
    const float* __restrict__ cloud_fraction,
    const float* __restrict__ T_0,
    float* __restrict__ out,
    int n)
{
    int p  = blockIdx.x * blockDim.x + threadIdx.x;
    int i0 = 2 * p;
    if (i0 >= n) return;
    bool has2 = (i0 + 1) < n;

    // float2 loads (i0 even -> 8B aligned); scalar fallback duplicates lane 0.
    #define LD2(ptr) (has2 ? *reinterpret_cast<const float2*>((ptr) + i0) \
                           : make_float2((ptr)[i0], (ptr)[i0]))
    float2 ta  = LD2(T_a);
    float2 ea  = LD2(e_a);
    float2 st  = LD2(shade_total);
    float2 cf  = LD2(cloud_fraction);
    float2 Ein = LD2(E);
    float2 el  = LD2(elev);
    float2 tg  = LD2(T_g);
    float2 sf  = LD2(sfr);
    float2 al  = LD2(albedo);
    float2 sw  = LD2(swrad);
    float2 t0  = LD2(T_0);
    #undef LD2

    float BA, CA, C2A, DA, BB, CB, C2B, DB;
    prologue(ta.x, ea.x, st.x, cf.x, Ein.x, el.x, tg.x, sf.x, al.x, sw.x,
             BA, CA, C2A, DA);
    prologue(ta.y, ea.y, st.y, cf.y, Ein.y, el.y, tg.y, sf.y, al.y, sw.y,
             BB, CB, C2B, DB);

    // Newton: 50 exact iterations as 25 pairs, two interleaved chains.
    float TeA = ta.x;
    float TeB = ta.y;
    #pragma unroll 5
    for (int j = 0; j < 25; ++j) {
        float a1 = newton_step(TeA, BA, CA, C2A, DA);
        float b1 = newton_step(TeB, BB, CB, C2B, DB);
        float a2 = newton_step(a1, BA, CA, C2A, DA);
        float b2 = newton_step(b1, BB, CB, C2B, DB);
        bool doneA = (a2 == a1) || (a2 == TeA);
        bool doneB = (b2 == b1) || (b2 == TeB);
        TeA = a2;
        TeB = b2;
        if (doneA && doneB) break;
        // closed chains keep pair-stepping: bit-exact (fixed point idempotent;
        // 2-cycle in pairs preserves even-parity value = s50).
    }

    float K1A, K2A, K1B, K2B;
    epilogue(TeA, t0.x, BA, CA, C2A, DA, K1A, K2A);
    epilogue(TeB, t0.y, BB, CB, C2B, DB, K1B, K2B);

    if (has2) {
        *reinterpret_cast<float2*>(out + i0)         = make_float2(TeA, TeB);
        *reinterpret_cast<float2*>(out + n + i0)     = make_float2(K1A, K1B);
        *reinterpret_cast<float2*>(out + 2 * n + i0) = make_float2(K2A, K2B);
    } else {
        out[i0]         = TeA;
        out[n + i0]     = K1A;
        out[2 * n + i0] = K2A;
    }
}

extern "C" void kernel_launch(void* const* d_in, const int* in_sizes, int n_in,
                              void* d_out, int out_size) {
    // metadata order: T_a, swrad, e_a, E, elev, slope, top_width, up_inflow,
    // T_g, shade_fraction_riparian, albedo, shade_total, cloud_fraction, T_0
    const float* T_a    = (const float*)d_in[0];
    const float* swrad  = (const float*)d_in[1];
    const float* e_a    = (const float*)d_in[2];
    const float* E      = (const float*)d_in[3];
    const float* elev   = (const float*)d_in[4];
    const float* T_g    = (const float*)d_in[8];
    const float* sfr    = (const float*)d_in[9];
    const float* albedo = (const float*)d_in[10];
    const float* stot   = (const float*)d_in[11];
    const float* cf     = (const float*)d_in[12];
    const float* T_0    = (const float*)d_in[13];

    int n = in_sizes[0];
    float* out = (float*)d_out;

    int threads = 256;
    int pairs   = (n + 1) / 2;
    int blocks  = (pairs + threads - 1) / threads;
    sntemp_kernel<<<blocks, threads>>>(T_a, swrad, e_a, E, elev, T_g, sfr,
                                       albedo, stot, cf, T_0, out, n);
}